// round 15
// baseline (speedup 1.0000x reference)
#include <cuda_runtime.h>
#include <math.h>

#define LEVELS 16
#define MAXRES 2048
#define BMAX   (1 << 20)
#define NB     (1 << 18)          // 18-bit Morton bins (6 bits/axis)
#define SCAN_BLK 1024
#define NBLK   (NB / SCAN_BLK)    // 256
#define MAIN_THREADS 1024

struct LP { float resm1[LEVELS]; float fres[LEVELS]; };

// ---------------- scratch ----------------------------------------------------
__device__ unsigned int g_hist[NB];
__device__ unsigned int g_bsum[NBLK];     // raw per-scanblock sums
__device__ float4       g_spos[BMAX];

// ---------------- helpers ----------------------------------------------------
__device__ __forceinline__ int quantize(float c, float fres) {
    return (int)__fmul_rn(__fdiv_rn(c, fres), 2047.0f);
}

__device__ __forceinline__ unsigned int expand3(unsigned int v) {
    v = (v | (v << 16)) & 0x030000FFu;
    v = (v | (v <<  8)) & 0x0300F00Fu;
    v = (v | (v <<  4)) & 0x030C30C3u;
    v = (v | (v <<  2)) & 0x09249249u;
    return v;
}

__device__ __forceinline__ unsigned int morton_key(float x, float y, float z) {
    int ix = (int)(x * 64.0f), iy = (int)(y * 64.0f), iz = (int)(z * 64.0f);
    unsigned int kx = (unsigned int)max(0, min(63, ix));
    unsigned int ky = (unsigned int)max(0, min(63, iy));
    unsigned int kz = (unsigned int)max(0, min(63, iz));
    return expand3(kx) | (expand3(ky) << 1) | (expand3(kz) << 2);
}

// ---------------- sort pipeline (round-11 config: best measured) -------------
__global__ void zero_hist_kernel() {
    int i = blockIdx.x * blockDim.x + threadIdx.x;
    if (i < NB) g_hist[i] = 0u;
}

__global__ void hist_kernel(const float* __restrict__ positions, int B) {
    int i = blockIdx.x * blockDim.x + threadIdx.x;
    if (i >= B) return;
    float x = __ldcs(&positions[3*i+0]);
    float y = __ldcs(&positions[3*i+1]);
    float z = __ldcs(&positions[3*i+2]);
    atomicAdd(&g_hist[morton_key(x, y, z)], 1u);
}

__global__ void scanA_kernel() {
    __shared__ unsigned int s[SCAN_BLK];
    int tid = threadIdx.x;
    int gid = blockIdx.x * SCAN_BLK + tid;
    unsigned int v = g_hist[gid];
    s[tid] = v;
    __syncthreads();
    for (int off = 1; off < SCAN_BLK; off <<= 1) {
        unsigned int t = (tid >= off) ? s[tid - off] : 0u;
        __syncthreads();
        s[tid] += t;
        __syncthreads();
    }
    g_hist[gid] = s[tid] - v;                 // exclusive within scan-block
    if (tid == SCAN_BLK - 1) g_bsum[blockIdx.x] = s[tid];   // raw block sum
}

// scanB + scanC fused: every block scans the 256 raw block-sums locally.
__global__ void scatter_kernel(const float* __restrict__ positions, int B) {
    __shared__ unsigned int sb[NBLK];
    int tid = threadIdx.x;
    {
        unsigned int v = g_bsum[tid];           // blockDim == NBLK == 256
        sb[tid] = v;
        __syncthreads();
        for (int off = 1; off < NBLK; off <<= 1) {
            unsigned int t = (tid >= off) ? sb[tid - off] : 0u;
            __syncthreads();
            sb[tid] += t;
            __syncthreads();
        }
        sb[tid] -= v;                           // exclusive prefix of block sums
        __syncthreads();
    }
    int i = blockIdx.x * blockDim.x + tid;
    if (i >= B) return;
    float x = __ldcs(&positions[3*i+0]);
    float y = __ldcs(&positions[3*i+1]);
    float z = __ldcs(&positions[3*i+2]);
    unsigned int k = morton_key(x, y, z);
    unsigned int dst = sb[k / SCAN_BLK] + atomicAdd(&g_hist[k], 1u);
    __stcs(&g_spos[dst], make_float4(x, y, z, __int_as_float(i)));
}

// ---------------- main encoder: 2 lanes per point (x-corner pair packed) -----
// 1024-thread blocks: 512 Morton-contiguous points per SM-resident block for
// maximal L1 working-set coherence. Logic identical to the 303.5us kernel.
__global__ void __launch_bounds__(MAIN_THREADS) triplane_kernel(
    const float* __restrict__ table,
    float* __restrict__ out, int B, LP lp)
{
    int gtid  = blockIdx.x * MAIN_THREADS + threadIdx.x;
    int point = gtid >> 1;
    int d0    = gtid & 1;
    bool valid = (point < B);

    float4 p = __ldcs(&g_spos[valid ? point : 0]);
    float px = p.x, py = p.y, pz = p.z;
    int b = __float_as_int(p.w);

    const float2* t0 = (const float2*)table;          // plane0 (x,y)
    const float2* t1 = t0 + MAXRES*MAXRES;            // plane1 (y,z)
    const float2* t2 = t1 + MAXRES*MAXRES;            // plane2 (z,x)

    float r[LEVELS];   // this lane's feature only

#pragma unroll
    for (int l = 0; l < LEVELS; l++) {
        float resm1 = lp.resm1[l];
        float fres  = lp.fres[l];

        // exact reference arithmetic (mul then add, no contraction)
        float posx = __fadd_rn(__fmul_rn(px, resm1), 0.5f);
        float posy = __fadd_rn(__fmul_rn(py, resm1), 0.5f);
        float posz = __fadd_rn(__fmul_rn(pz, resm1), 0.5f);
        float gx = floorf(posx), gy = floorf(posy), gz = floorf(posz);
        float fx = posx - gx, fy = posy - gy, fz = posz - gz;

        int cx0 = quantize(gx, fres), cx1 = quantize(gx + 1.0f, fres);
        int cy0 = quantize(gy, fres), cy1 = quantize(gy + 1.0f, fres);
        int cz0 = quantize(gz, fres), cz1 = quantize(gz + 1.0f, fres);

        int cxd = d0 ? cx1 : cx0;     // this lane's first-axis coords
        int cyd = d0 ? cy1 : cy0;
        int czd = d0 ? cz1 : cz0;

        // 6 gathers: both second-axis corners at my first-axis corner, per plane
        float2 a0 = __ldg(&t0[cxd + cy0*MAXRES]);
        float2 a1 = __ldg(&t0[cxd + cy1*MAXRES]);
        float2 b0 = __ldg(&t1[cyd + cz0*MAXRES]);
        float2 b1 = __ldg(&t1[cyd + cz1*MAXRES]);
        float2 c0 = __ldg(&t2[czd + cx0*MAXRES]);
        float2 c1 = __ldg(&t2[czd + cx1*MAXRES]);

        float wxd = d0 ? fx : (1.0f - fx);
        float wyd = d0 ? fy : (1.0f - fy);
        float wzd = d0 ? fz : (1.0f - fz);
        float wy0 = 1.0f - fy, wy1 = fy;
        float wz0 = 1.0f - fz, wz1 = fz;
        float wx0 = 1.0f - fx, wx1 = fx;

        float pax = wxd * (wy0*a0.x + wy1*a1.x);
        float pay = wxd * (wy0*a0.y + wy1*a1.y);
        float pbx = wyd * (wz0*b0.x + wz1*b1.x);
        float pby = wyd * (wz0*b0.y + wz1*b1.y);
        float pcx = wzd * (wx0*c0.x + wx1*c1.x);
        float pcy = wzd * (wx0*c0.y + wx1*c1.y);

        // cross-lane pair sum -> full bilinear value in both lanes
        pax += __shfl_xor_sync(0xFFFFFFFFu, pax, 1);
        pay += __shfl_xor_sync(0xFFFFFFFFu, pay, 1);
        pbx += __shfl_xor_sync(0xFFFFFFFFu, pbx, 1);
        pby += __shfl_xor_sync(0xFFFFFFFFu, pby, 1);
        pcx += __shfl_xor_sync(0xFFFFFFFFu, pcx, 1);
        pcy += __shfl_xor_sync(0xFFFFFFFFu, pcy, 1);

        float vx = (pax * pbx) * pcx;
        float vy = (pay * pby) * pcy;
        r[l] = d0 ? vy : vx;          // lane keeps its own feature
    }

    if (valid) {
        float4* oh = (float4*)(out + (size_t)b * (2*LEVELS) + d0 * LEVELS);
#pragma unroll
        for (int k = 0; k < 4; k++)
            __stcs(&oh[k], make_float4(r[4*k+0], r[4*k+1], r[4*k+2], r[4*k+3]));
    }
}

// ---------------- launch -----------------------------------------------------
extern "C" void kernel_launch(void* const* d_in, const int* in_sizes, int n_in,
                              void* d_out, int out_size) {
    const float* positions = (const float*)d_in[0];
    const float* table     = (const float*)d_in[1];
    float* out             = (float*)d_out;
    int B = in_sizes[0] / 3;

    LP lp;
    double logb = log(2048.0 / 16.0) / 15.0;
    for (int l = 0; l < LEVELS; l++) {
        double scale = 16.0 * exp((double)l * logb) - 1.0;
        int res = (int)ceil(scale) + 1;
        lp.resm1[l] = (float)(res - 1);
        lp.fres[l]  = (float)res;
    }

    int threads = 256;
    int blocksP = (B + threads - 1) / threads;                 // 1 thread/point kernels
    int blocksM = (2*B + MAIN_THREADS - 1) / MAIN_THREADS;     // 2 lanes per point

    zero_hist_kernel<<<NB / 256, 256>>>();
    hist_kernel<<<blocksP, threads>>>(positions, B);
    scanA_kernel<<<NBLK, SCAN_BLK>>>();
    scatter_kernel<<<blocksP, threads>>>(positions, B);
    triplane_kernel<<<blocksM, MAIN_THREADS>>>(table, out, B, lp);
}

// round 16
// speedup vs baseline: 1.1481x; 1.1481x over previous
#include <cuda_runtime.h>
#include <math.h>

#define LEVELS 16
#define MAXRES 2048
#define BMAX   (1 << 20)
#define NB     (1 << 18)          // 18-bit Morton bins (6 bits/axis)
#define SCAN_BLK 1024
#define NBLK   (NB / SCAN_BLK)    // 256
#define MAIN_THREADS 512

struct LP { float resm1[LEVELS]; float fres[LEVELS]; };

// ---------------- scratch ----------------------------------------------------
__device__ unsigned int g_hist[NB];
__device__ unsigned int g_bsum[NBLK];     // raw per-scanblock sums
__device__ float4       g_spos[BMAX];

// ---------------- helpers ----------------------------------------------------
__device__ __forceinline__ int quantize(float c, float fres) {
    return (int)__fmul_rn(__fdiv_rn(c, fres), 2047.0f);
}

__device__ __forceinline__ unsigned int expand3(unsigned int v) {
    v = (v | (v << 16)) & 0x030000FFu;
    v = (v | (v <<  8)) & 0x0300F00Fu;
    v = (v | (v <<  4)) & 0x030C30C3u;
    v = (v | (v <<  2)) & 0x09249249u;
    return v;
}

__device__ __forceinline__ unsigned int morton_key(float x, float y, float z) {
    int ix = (int)(x * 64.0f), iy = (int)(y * 64.0f), iz = (int)(z * 64.0f);
    unsigned int kx = (unsigned int)max(0, min(63, ix));
    unsigned int ky = (unsigned int)max(0, min(63, iy));
    unsigned int kz = (unsigned int)max(0, min(63, iz));
    return expand3(kx) | (expand3(ky) << 1) | (expand3(kz) << 2);
}

// ---------------- sort pipeline (round-11 config: best measured) -------------
__global__ void zero_hist_kernel() {
    int i = blockIdx.x * blockDim.x + threadIdx.x;
    if (i < NB) g_hist[i] = 0u;
}

__global__ void hist_kernel(const float* __restrict__ positions, int B) {
    int i = blockIdx.x * blockDim.x + threadIdx.x;
    if (i >= B) return;
    float x = __ldcs(&positions[3*i+0]);
    float y = __ldcs(&positions[3*i+1]);
    float z = __ldcs(&positions[3*i+2]);
    atomicAdd(&g_hist[morton_key(x, y, z)], 1u);
}

__global__ void scanA_kernel() {
    __shared__ unsigned int s[SCAN_BLK];
    int tid = threadIdx.x;
    int gid = blockIdx.x * SCAN_BLK + tid;
    unsigned int v = g_hist[gid];
    s[tid] = v;
    __syncthreads();
    for (int off = 1; off < SCAN_BLK; off <<= 1) {
        unsigned int t = (tid >= off) ? s[tid - off] : 0u;
        __syncthreads();
        s[tid] += t;
        __syncthreads();
    }
    g_hist[gid] = s[tid] - v;                 // exclusive within scan-block
    if (tid == SCAN_BLK - 1) g_bsum[blockIdx.x] = s[tid];   // raw block sum
}

// scanB + scanC fused: every block scans the 256 raw block-sums locally.
__global__ void scatter_kernel(const float* __restrict__ positions, int B) {
    __shared__ unsigned int sb[NBLK];
    int tid = threadIdx.x;
    {
        unsigned int v = g_bsum[tid];           // blockDim == NBLK == 256
        sb[tid] = v;
        __syncthreads();
        for (int off = 1; off < NBLK; off <<= 1) {
            unsigned int t = (tid >= off) ? sb[tid - off] : 0u;
            __syncthreads();
            sb[tid] += t;
            __syncthreads();
        }
        sb[tid] -= v;                           // exclusive prefix of block sums
        __syncthreads();
    }
    int i = blockIdx.x * blockDim.x + tid;
    if (i >= B) return;
    float x = __ldcs(&positions[3*i+0]);
    float y = __ldcs(&positions[3*i+1]);
    float z = __ldcs(&positions[3*i+2]);
    unsigned int k = morton_key(x, y, z);
    unsigned int dst = sb[k / SCAN_BLK] + atomicAdd(&g_hist[k], 1u);
    __stcs(&g_spos[dst], make_float4(x, y, z, __int_as_float(i)));
}

// ---------------- main encoder: 2 lanes per point (x-corner pair packed) -----
// 512-thread blocks (best measured: 303.5us), zero smem + MaxL1 carveout.
__global__ void __launch_bounds__(MAIN_THREADS) triplane_kernel(
    const float* __restrict__ table,
    float* __restrict__ out, int B, LP lp)
{
    int gtid  = blockIdx.x * MAIN_THREADS + threadIdx.x;
    int point = gtid >> 1;
    int d0    = gtid & 1;
    bool valid = (point < B);

    float4 p = __ldcs(&g_spos[valid ? point : 0]);
    float px = p.x, py = p.y, pz = p.z;
    int b = __float_as_int(p.w);

    const float2* t0 = (const float2*)table;          // plane0 (x,y)
    const float2* t1 = t0 + MAXRES*MAXRES;            // plane1 (y,z)
    const float2* t2 = t1 + MAXRES*MAXRES;            // plane2 (z,x)

    float r[LEVELS];   // this lane's feature only

#pragma unroll
    for (int l = 0; l < LEVELS; l++) {
        float resm1 = lp.resm1[l];
        float fres  = lp.fres[l];

        // exact reference arithmetic (mul then add, no contraction)
        float posx = __fadd_rn(__fmul_rn(px, resm1), 0.5f);
        float posy = __fadd_rn(__fmul_rn(py, resm1), 0.5f);
        float posz = __fadd_rn(__fmul_rn(pz, resm1), 0.5f);
        float gx = floorf(posx), gy = floorf(posy), gz = floorf(posz);
        float fx = posx - gx, fy = posy - gy, fz = posz - gz;

        int cx0 = quantize(gx, fres), cx1 = quantize(gx + 1.0f, fres);
        int cy0 = quantize(gy, fres), cy1 = quantize(gy + 1.0f, fres);
        int cz0 = quantize(gz, fres), cz1 = quantize(gz + 1.0f, fres);

        int cxd = d0 ? cx1 : cx0;     // this lane's first-axis coords
        int cyd = d0 ? cy1 : cy0;
        int czd = d0 ? cz1 : cz0;

        // 6 gathers: both second-axis corners at my first-axis corner, per plane
        float2 a0 = __ldg(&t0[cxd + cy0*MAXRES]);
        float2 a1 = __ldg(&t0[cxd + cy1*MAXRES]);
        float2 b0 = __ldg(&t1[cyd + cz0*MAXRES]);
        float2 b1 = __ldg(&t1[cyd + cz1*MAXRES]);
        float2 c0 = __ldg(&t2[czd + cx0*MAXRES]);
        float2 c1 = __ldg(&t2[czd + cx1*MAXRES]);

        float wxd = d0 ? fx : (1.0f - fx);
        float wyd = d0 ? fy : (1.0f - fy);
        float wzd = d0 ? fz : (1.0f - fz);
        float wy0 = 1.0f - fy, wy1 = fy;
        float wz0 = 1.0f - fz, wz1 = fz;
        float wx0 = 1.0f - fx, wx1 = fx;

        float pax = wxd * (wy0*a0.x + wy1*a1.x);
        float pay = wxd * (wy0*a0.y + wy1*a1.y);
        float pbx = wyd * (wz0*b0.x + wz1*b1.x);
        float pby = wyd * (wz0*b0.y + wz1*b1.y);
        float pcx = wzd * (wx0*c0.x + wx1*c1.x);
        float pcy = wzd * (wx0*c0.y + wx1*c1.y);

        // cross-lane pair sum -> full bilinear value in both lanes
        pax += __shfl_xor_sync(0xFFFFFFFFu, pax, 1);
        pay += __shfl_xor_sync(0xFFFFFFFFu, pay, 1);
        pbx += __shfl_xor_sync(0xFFFFFFFFu, pbx, 1);
        pby += __shfl_xor_sync(0xFFFFFFFFu, pby, 1);
        pcx += __shfl_xor_sync(0xFFFFFFFFu, pcx, 1);
        pcy += __shfl_xor_sync(0xFFFFFFFFu, pcy, 1);

        float vx = (pax * pbx) * pcx;
        float vy = (pay * pby) * pcy;
        r[l] = d0 ? vy : vx;          // lane keeps its own feature
    }

    if (valid) {
        float4* oh = (float4*)(out + (size_t)b * (2*LEVELS) + d0 * LEVELS);
#pragma unroll
        for (int k = 0; k < 4; k++)
            __stcs(&oh[k], make_float4(r[4*k+0], r[4*k+1], r[4*k+2], r[4*k+3]));
    }
}

// ---------------- launch -----------------------------------------------------
extern "C" void kernel_launch(void* const* d_in, const int* in_sizes, int n_in,
                              void* d_out, int out_size) {
    const float* positions = (const float*)d_in[0];
    const float* table     = (const float*)d_in[1];
    float* out             = (float*)d_out;
    int B = in_sizes[0] / 3;

    // Maximize L1D for the gather kernel (it uses no shared memory).
    // Host-side attribute set; executes immediately, graph-capture safe.
    static bool carveout_set = false;
    if (!carveout_set) {
        cudaFuncSetAttribute(triplane_kernel,
                             cudaFuncAttributePreferredSharedMemoryCarveout,
                             cudaSharedmemCarveoutMaxL1);
        carveout_set = true;
    }

    LP lp;
    double logb = log(2048.0 / 16.0) / 15.0;
    for (int l = 0; l < LEVELS; l++) {
        double scale = 16.0 * exp((double)l * logb) - 1.0;
        int res = (int)ceil(scale) + 1;
        lp.resm1[l] = (float)(res - 1);
        lp.fres[l]  = (float)res;
    }

    int threads = 256;
    int blocksP = (B + threads - 1) / threads;                 // 1 thread/point kernels
    int blocksM = (2*B + MAIN_THREADS - 1) / MAIN_THREADS;     // 2 lanes per point

    zero_hist_kernel<<<NB / 256, 256>>>();
    hist_kernel<<<blocksP, threads>>>(positions, B);
    scanA_kernel<<<NBLK, SCAN_BLK>>>();
    scatter_kernel<<<blocksP, threads>>>(positions, B);
    triplane_kernel<<<blocksM, MAIN_THREADS>>>(table, out, B, lp);
}